// round 6
// baseline (speedup 1.0000x reference)
#include <cuda_runtime.h>

#define NT 25            // edge types
#define NMAX 50176       // node capacity (N=50000)

__device__ float g_h   [NMAX * 16];
__device__ float g_h2  [NMAX * 16];
__device__ float g_aggT[16 * NMAX];   // TRANSPOSED: [o][n] so per-edge scatter spreads across L2 slices
__device__ int   g_deg [NMAX];
__device__ float g_pool[64 * 16];
__device__ int   g_pcnt[64];

// ---------------------------------------------------------------- fused edge NN + message + scatter
// Per-type factorization: w[t,i,o](ef) = relu(ef0*C0 + ef1*C1 + C2),
//   C0 = emb*wh0 + wg0, C1 = emb*wh1 + wg1, C2 = emb*bh + bg.
// Tables built per block into smem (48KB). 16-lane group per edge, lane = o.
template <int IN, int OUT, bool DEG>
__global__ __launch_bounds__(256)
void edge_kernel(const float* __restrict__ xext, int xsel,
                 const float2* __restrict__ ef,
                 const int*   __restrict__ etype,
                 const int*   __restrict__ esrc,
                 const int*   __restrict__ edst,
                 const float* __restrict__ emb,
                 const float* __restrict__ wh,
                 const float* __restrict__ bh,
                 const float* __restrict__ wg,
                 const float* __restrict__ bg,
                 int E)
{
    constexpr int D = IN * OUT;                 // 160
    __shared__ float2 sC01[NT * D];             // 32000 B
    __shared__ float  sC2 [NT * D];             // 16000 B

    for (int j = threadIdx.x; j < NT * D; j += blockDim.x) {
        int t = j / D, k = j - t * D;
        float e = __ldg(&emb[j]);
        sC01[j] = make_float2(fmaf(e, __ldg(&wh[k]),     __ldg(&wg[k])),
                              fmaf(e, __ldg(&wh[D + k]), __ldg(&wg[D + k])));
        sC2[j]  = fmaf(e, __ldg(&bh[k]), __ldg(&bg[k]));
        (void)t;
    }
    __syncthreads();

    const float* x = (xsel == 0) ? xext : (xsel == 1 ? g_h : g_h2);

    int o  = threadIdx.x & 15;
    int oc = (o < OUT) ? o : 0;
    unsigned gmask = 0xFFFFu << (threadIdx.x & 16);   // proper mask for width-16 shfl

    int group = (blockIdx.x * blockDim.x + threadIdx.x) >> 4;
    int ng    = (gridDim.x * blockDim.x) >> 4;

    int e = group;
    int et = 0, s = 0, d = 0; float ef0 = 0.f, ef1 = 0.f, xv = 0.f;
    if (e < E) {
        et = etype[e]; s = esrc[e]; d = edst[e];
        float2 f = ef[e]; ef0 = f.x; ef1 = f.y;
        xv = x[s * 16 + o];
    }
    while (e < E) {
        // software pipeline: prefetch next edge
        int e2 = e + ng;
        int et2 = 0, s2 = 0, d2 = 0; float ef02 = 0.f, ef12 = 0.f, xv2 = 0.f;
        if (e2 < E) {
            et2 = etype[e2]; s2 = esrc[e2]; d2 = edst[e2];
            float2 f = ef[e2]; ef02 = f.x; ef12 = f.y;
            xv2 = x[s2 * 16 + o];
        }

        int base = et * D + oc;
        float acc0 = 0.f, acc1 = 0.f;
#pragma unroll
        for (int i = 0; i < IN; i += 2) {
            {
                float2 c = sC01[base + i * OUT];
                float  w = fmaxf(fmaf(ef1, c.y, fmaf(ef0, c.x, sC2[base + i * OUT])), 0.f);
                acc0 = fmaf(__shfl_sync(gmask, xv, i, 16), w, acc0);
            }
            {
                float2 c = sC01[base + (i + 1) * OUT];
                float  w = fmaxf(fmaf(ef1, c.y, fmaf(ef0, c.x, sC2[base + (i + 1) * OUT])), 0.f);
                acc1 = fmaf(__shfl_sync(gmask, xv, i + 1, 16), w, acc1);
            }
        }
        if (o < OUT) atomicAdd(&g_aggT[o * NMAX + d], acc0 + acc1);
        if (DEG && o == 0) atomicAdd(&g_deg[d], 1);

        e = e2; et = et2; s = s2; d = d2; ef0 = ef02; ef1 = ef12; xv = xv2;
    }
}

// ---------------------------------------------------------------- node update: relu(agg/deg + x@root + bias)
// ONE thread per node: 16 independent accumulator chains, transposed-agg reads
// coalesced across the warp, root/bias staged in smem. Self-cleans g_aggT.
// POOL: block-local smem pooling (batch_ids sorted -> ~1 bucket per block).
template <int IN, int OUT, bool POOL>
__global__ __launch_bounds__(256)
void node_kernel(const float* __restrict__ xext, int xsel, int osel,
                 const float* __restrict__ root,
                 const float* __restrict__ bias,
                 const int*   __restrict__ ctype,
                 const int*   __restrict__ bids,
                 int N, int B)
{
    __shared__ float s_root[IN * OUT];
    __shared__ float s_bias[OUT];
    __shared__ float s_pool[64 * 16];
    __shared__ int   s_cnt [64];

    int tid = threadIdx.x;
    for (int j = tid; j < IN * OUT; j += 256) s_root[j] = __ldg(&root[j]);
    if (tid < OUT) s_bias[tid] = __ldg(&bias[tid]);
    if (POOL) {
        for (int j = tid; j < B * 16; j += 256) s_pool[j] = 0.f;
        if (tid < B) s_cnt[tid] = 0;
    }
    __syncthreads();

    const float* x    = (xsel == 0) ? xext : (xsel == 1 ? g_h : g_h2);
    float*       hout = (osel == 1) ? g_h : g_h2;

    int n = blockIdx.x * 256 + tid;
    if (n < N) {
        int   dg  = g_deg[n];
        float inv = __frcp_rn((float)(dg > 0 ? dg : 1));

        float a[OUT];
#pragma unroll
        for (int o = 0; o < OUT; o++) {
            float v = g_aggT[o * NMAX + n];
            g_aggT[o * NMAX + n] = 0.f;              // self-cleaning
            a[o] = fmaf(v, inv, s_bias[o]);
        }

        float xv[IN];
        {
            const float4* xr = (const float4*)(x + n * 16);
            float4 v0 = __ldg(&xr[0]);
            float4 v1 = __ldg(&xr[1]);
            xv[0] = v0.x; xv[1] = v0.y; xv[2] = v0.z; xv[3] = v0.w;
            xv[4] = v1.x; xv[5] = v1.y; xv[6] = v1.z; xv[7] = v1.w;
            if constexpr (IN == 16) {
                float4 v2 = __ldg(&xr[2]);
                float4 v3 = __ldg(&xr[3]);
                xv[8]  = v2.x; xv[9]  = v2.y; xv[10] = v2.z; xv[11] = v2.w;
                xv[12] = v3.x; xv[13] = v3.y; xv[14] = v3.z; xv[15] = v3.w;
            } else {
                float2 v2 = __ldg(&((const float2*)xr)[4]);
                xv[8] = v2.x; xv[9] = v2.y;
            }
        }

#pragma unroll
        for (int i = 0; i < IN; i++)
#pragma unroll
            for (int o = 0; o < OUT; o++)
                a[o] = fmaf(xv[i], s_root[i * OUT + o], a[o]);

#pragma unroll
        for (int o = 0; o < OUT; o++) a[o] = fmaxf(a[o], 0.f);

        if (POOL) {
            if (ctype[n] == 1) {
                int b = bids[n];
#pragma unroll
                for (int o = 0; o < OUT; o++) atomicAdd(&s_pool[b * 16 + o], a[o]);
                atomicAdd(&s_cnt[b], 1);
            }
            g_deg[n] = 0;                            // reset for next replay
        } else {
#pragma unroll
            for (int o = 0; o < OUT; o++) hout[n * 16 + o] = a[o];
        }
    }

    if (POOL) {
        __syncthreads();
        for (int j = tid; j < B * 16; j += 256) {
            float v = s_pool[j];
            if (v != 0.f) atomicAdd(&g_pool[j], v);
        }
        for (int j = tid; j < B; j += 256) {
            int c = s_cnt[j];
            if (c) atomicAdd(&g_pcnt[j], c);
        }
    }
}

// ---------------------------------------------------------------- final: divide + emit, then reset pool state
__global__ void final_kernel(float* __restrict__ out, int nsz) {
    int idx = threadIdx.x;
    if (idx < nsz) {
        int b = idx >> 4;
        int c = g_pcnt[b];
        out[idx] = g_pool[idx] / (float)(c > 0 ? c : 1);
    }
    __syncthreads();
    for (int j = idx; j < 64 * 16; j += blockDim.x) g_pool[j] = 0.f;
    if (idx < 64) g_pcnt[idx] = 0;
}

// ---------------------------------------------------------------- launch
extern "C" void kernel_launch(void* const* d_in, const int* in_sizes, int n_in,
                              void* d_out, int out_size)
{
    bool setup_order = (in_sizes[2] == in_sizes[3]) && (in_sizes[3] == in_sizes[4]);

    const float* x     = (const float*)d_in[0];
    const float* efeat = (const float*)d_in[1];
    const int *etype, *esrc, *edst, *ctype, *bids;
    const float *emb[3], *wh[3], *bhp[3], *wg[3], *bgp[3], *root[3], *bias[3];
    int pbase, eidx, cidx;

    if (setup_order) {
        etype = (const int*)d_in[2];  esrc = (const int*)d_in[3];  edst = (const int*)d_in[4];
        ctype = (const int*)d_in[5];  bids = (const int*)d_in[6];
        pbase = 8; eidx = 2; cidx = 5;
    } else {
        etype = (const int*)d_in[23]; esrc = (const int*)d_in[24]; edst = (const int*)d_in[25];
        ctype = (const int*)d_in[26]; bids = (const int*)d_in[27];
        pbase = 2; eidx = 23; cidx = 26;
    }
    for (int l = 0; l < 3; l++) {
        int b0 = pbase + l * 7;
        emb[l]  = (const float*)d_in[b0];
        wh[l]   = (const float*)d_in[b0 + 1];
        bhp[l]  = (const float*)d_in[b0 + 2];
        wg[l]   = (const float*)d_in[b0 + 3];
        bgp[l]  = (const float*)d_in[b0 + 4];
        root[l] = (const float*)d_in[b0 + 5];
        bias[l] = (const float*)d_in[b0 + 6];
    }
    int E = in_sizes[eidx];
    int N = in_sizes[cidx];
    int B = out_size / 16;
    float* out = (float*)d_out;

    const int EB = 592, ET = 256;            // 4 blocks/SM resident, grid-stride edges
    int NB = (N + 255) / 256;

    // layer 1: 16 -> 10  (also accumulates degree)
    edge_kernel<16, 10, true ><<<EB, ET>>>(x, 0, (const float2*)efeat, etype, esrc, edst,
                                           emb[0], wh[0], bhp[0], wg[0], bgp[0], E);
    node_kernel<16, 10, false><<<NB, 256>>>(x, 0, 1, root[0], bias[0], nullptr, nullptr, N, B);

    // layer 2: 10 -> 10
    edge_kernel<10, 10, false><<<EB, ET>>>(x, 1, (const float2*)efeat, etype, esrc, edst,
                                           emb[1], wh[1], bhp[1], wg[1], bgp[1], E);
    node_kernel<10, 10, false><<<NB, 256>>>(x, 1, 2, root[1], bias[1], nullptr, nullptr, N, B);

    // layer 3: 10 -> 16  (fused block-local pooling, zeroes deg)
    edge_kernel<10, 16, false><<<EB, ET>>>(x, 2, (const float2*)efeat, etype, esrc, edst,
                                           emb[2], wh[2], bhp[2], wg[2], bgp[2], E);
    node_kernel<10, 16, true ><<<NB, 256>>>(x, 2, 0, root[2], bias[2], ctype, bids, N, B);

    final_kernel<<<1, 256>>>(out, out_size);
}

// round 7
// speedup vs baseline: 1.0903x; 1.0903x over previous
#include <cuda_runtime.h>

#define NT   25          // edge types
#define NMAX 50176       // node capacity (N=50000)
#define EMAX 250112      // edge capacity (E=250000)

__device__ float  g_h  [NMAX * 16];
__device__ float  g_h2 [NMAX * 16];
__device__ int    g_rowcnt[NMAX];
__device__ int    g_rowptr[NMAX + 1];
__device__ int    g_wcur  [NMAX];
__device__ int    g_bsum[256];
__device__ int    g_boff[256];
__device__ int4   g_epack[EMAX];        // CSR-ordered {etype, src, ef0_bits, ef1_bits}
__device__ float2 g_C01[3][NT * 160];   // per-type factored edge-NN tables
__device__ float  g_C2 [3][NT * 160];
__device__ float  g_pool[64 * 16];
__device__ int    g_pcnt[64];

// ---------------------------------------------------------------- prep: zero histogram + build C tables
// w[t,i,o](ef) = relu(ef0*C0 + ef1*C1 + C2);  C0=emb*wh0+wg0, C1=emb*wh1+wg1, C2=emb*bh+bg
__global__ void prep_kernel(
    const float* __restrict__ e1, const float* __restrict__ wh1, const float* __restrict__ bh1,
    const float* __restrict__ wg1, const float* __restrict__ bg1,
    const float* __restrict__ e2, const float* __restrict__ wh2, const float* __restrict__ bh2,
    const float* __restrict__ wg2, const float* __restrict__ bg2,
    const float* __restrict__ e3, const float* __restrict__ wh3, const float* __restrict__ bh3,
    const float* __restrict__ wg3, const float* __restrict__ bg3,
    int N)
{
    int j = blockIdx.x * blockDim.x + threadIdx.x;
    if (j < N) g_rowcnt[j] = 0;
    if (j < NT * 160) {                       // layer 1: D=160
        int k = j % 160; float e = e1[j];
        g_C01[0][j] = make_float2(fmaf(e, wh1[k], wg1[k]), fmaf(e, wh1[160 + k], wg1[160 + k]));
        g_C2 [0][j] = fmaf(e, bh1[k], bg1[k]);
    }
    if (j < NT * 100) {                       // layer 2: D=100
        int k = j % 100; float e = e2[j];
        g_C01[1][j] = make_float2(fmaf(e, wh2[k], wg2[k]), fmaf(e, wh2[100 + k], wg2[100 + k]));
        g_C2 [1][j] = fmaf(e, bh2[k], bg2[k]);
    }
    if (j < NT * 160) {                       // layer 3: D=160
        int k = j % 160; float e = e3[j];
        g_C01[2][j] = make_float2(fmaf(e, wh3[k], wg3[k]), fmaf(e, wh3[160 + k], wg3[160 + k]));
        g_C2 [2][j] = fmaf(e, bh3[k], bg3[k]);
    }
}

// ---------------------------------------------------------------- CSR build
__global__ void hist_kernel(const int* __restrict__ edst, int E) {
    int e = blockIdx.x * blockDim.x + threadIdx.x;
    if (e < E) atomicAdd(&g_rowcnt[edst[e]], 1);
}

__global__ void scan1_kernel(int N) {         // per-block sums of rowcnt
    __shared__ int s[256];
    int n = blockIdx.x * 256 + threadIdx.x;
    s[threadIdx.x] = (n < N) ? g_rowcnt[n] : 0;
    __syncthreads();
    for (int off = 128; off > 0; off >>= 1) {
        if (threadIdx.x < off) s[threadIdx.x] += s[threadIdx.x + off];
        __syncthreads();
    }
    if (threadIdx.x == 0) g_bsum[blockIdx.x] = s[0];
}

__global__ void scan2_kernel(int NB) {        // exclusive scan of block sums (NB <= 256)
    __shared__ int s[256];
    int t = threadIdx.x;
    int v = (t < NB) ? g_bsum[t] : 0;
    s[t] = v;
    __syncthreads();
    for (int off = 1; off < 256; off <<= 1) {
        int u = (t >= off) ? s[t - off] : 0;
        __syncthreads();
        s[t] += u;
        __syncthreads();
    }
    if (t < NB) g_boff[t] = s[t] - v;         // exclusive
}

__global__ void scan3_kernel(int N, int E) {  // rowptr = boff + block-local exclusive scan
    __shared__ int s[256];
    int t = threadIdx.x;
    int n = blockIdx.x * 256 + t;
    int v = (n < N) ? g_rowcnt[n] : 0;
    s[t] = v;
    __syncthreads();
    for (int off = 1; off < 256; off <<= 1) {
        int u = (t >= off) ? s[t - off] : 0;
        __syncthreads();
        s[t] += u;
        __syncthreads();
    }
    if (n < N) {
        int start = g_boff[blockIdx.x] + s[t] - v;
        g_rowptr[n] = start;
        g_wcur[n]   = start;
        if (n == N - 1) g_rowptr[N] = E;
    }
}

__global__ void scatter_kernel(const int* __restrict__ etype,
                               const int* __restrict__ esrc,
                               const int* __restrict__ edst,
                               const float2* __restrict__ ef, int E) {
    int e = blockIdx.x * blockDim.x + threadIdx.x;
    if (e < E) {
        int p = atomicAdd(&g_wcur[edst[e]], 1);
        float2 f = ef[e];
        g_epack[p] = make_int4(etype[e], esrc[e], __float_as_int(f.x), __float_as_int(f.y));
    }
}

// ---------------------------------------------------------------- fused layer: gather messages + node update (+pool)
// 16-lane group per node (lane = output col o). Edges batched 4-deep for MLP.
// Zero global atomics in the heavy path.
template <int IN, int OUT, int L, bool POOL>
__global__ __launch_bounds__(256)
void layer_kernel(const float* __restrict__ xext,
                  const float* __restrict__ root,
                  const float* __restrict__ bias,
                  const int*   __restrict__ ctype,
                  const int*   __restrict__ bids,
                  int N)
{
    constexpr int D = IN * OUT;
    __shared__ float2 sC01[NT * D];
    __shared__ float  sC2 [NT * D];
    __shared__ float  s_pool[8 * 16];
    __shared__ int    s_cnt [8];

    for (int j = threadIdx.x; j < NT * D; j += 256) {
        sC01[j] = g_C01[L][j];
        sC2 [j] = g_C2 [L][j];
    }
    if (POOL) {
        if (threadIdx.x < 8 * 16) s_pool[threadIdx.x] = 0.f;
        if (threadIdx.x < 8)      s_cnt [threadIdx.x] = 0;
    }
    __syncthreads();

    const float* xin  = (L == 0) ? xext : (L == 1 ? g_h : g_h2);
    float*       hout = (L == 0) ? g_h : g_h2;

    int o  = threadIdx.x & 15;
    int oc = (o < OUT) ? o : 0;
    bool lo = (o < IN);
    unsigned gmask = 0xFFFFu << (threadIdx.x & 16);

    float rreg[IN];
#pragma unroll
    for (int i = 0; i < IN; i++) rreg[i] = __ldg(&root[i * OUT + oc]);
    float bv = __ldg(&bias[oc]);

    int group = (blockIdx.x * blockDim.x + threadIdx.x) >> 4;
    int ng    = (gridDim.x * blockDim.x) >> 4;

    auto eterm = [&](int4 ep, float xv, float acc) -> float {
        int base = ep.x * D + oc;
        float ef0 = __int_as_float(ep.z), ef1 = __int_as_float(ep.w);
#pragma unroll
        for (int i = 0; i < IN; i++) {
            float2 c = sC01[base + i * OUT];
            float  w = fmaxf(fmaf(ef1, c.y, fmaf(ef0, c.x, sC2[base + i * OUT])), 0.f);
            acc = fmaf(__shfl_sync(gmask, xv, i, 16), w, acc);
        }
        return acc;
    };

    for (int n = group; n < N; n += ng) {
        int r0 = __ldg(&g_rowptr[n]);
        int r1 = __ldg(&g_rowptr[n + 1]);
        float acc0 = 0.f, acc1 = 0.f;

        for (int p = r0; p < r1; p += 4) {
            int m = r1 - p;                    // uniform across the 16-lane group
            int4 ep0, ep1, ep2, ep3;
            ep0 = g_epack[p];
            if (m > 1) ep1 = g_epack[p + 1];
            if (m > 2) ep2 = g_epack[p + 2];
            if (m > 3) ep3 = g_epack[p + 3];
            float xv0 = 0.f, xv1 = 0.f, xv2 = 0.f, xv3 = 0.f;
            if (lo)          xv0 = xin[ep0.y * 16 + o];
            if (m > 1 && lo) xv1 = xin[ep1.y * 16 + o];
            if (m > 2 && lo) xv2 = xin[ep2.y * 16 + o];
            if (m > 3 && lo) xv3 = xin[ep3.y * 16 + o];

            acc0 = eterm(ep0, xv0, acc0);
            if (m > 1) acc1 = eterm(ep1, xv1, acc1);
            if (m > 2) acc0 = eterm(ep2, xv2, acc0);
            if (m > 3) acc1 = eterm(ep3, xv3, acc1);
        }

        int deg = r1 - r0;
        float inv = __frcp_rn((float)(deg > 0 ? deg : 1));
        float a = fmaf(acc0 + acc1, inv, bv);

        float xn = lo ? xin[n * 16 + o] : 0.f;
#pragma unroll
        for (int i = 0; i < IN; i++)
            a = fmaf(__shfl_sync(gmask, xn, i, 16), rreg[i], a);
        a = fmaxf(a, 0.f);

        if (POOL) {
            if (__ldg(&ctype[n]) == 1) {
                int b = __ldg(&bids[n]);
                atomicAdd(&s_pool[b * 16 + o], a);
                if (o == 0) atomicAdd(&s_cnt[b], 1);
            }
        } else {
            if (o < OUT) hout[n * 16 + o] = a;
        }
    }

    if (POOL) {
        __syncthreads();
        if (threadIdx.x < 8 * 16) {
            float v = s_pool[threadIdx.x];
            if (v != 0.f) atomicAdd(&g_pool[threadIdx.x], v);
        }
        if (threadIdx.x < 8) {
            int c = s_cnt[threadIdx.x];
            if (c) atomicAdd(&g_pcnt[threadIdx.x], c);
        }
    }
}

// ---------------------------------------------------------------- final: divide + emit, reset pool state
__global__ void final_kernel(float* __restrict__ out, int nsz) {
    int idx = threadIdx.x;
    if (idx < nsz) {
        int b = idx >> 4;
        int c = g_pcnt[b];
        out[idx] = g_pool[idx] / (float)(c > 0 ? c : 1);
    }
    __syncthreads();
    for (int j = idx; j < 64 * 16; j += blockDim.x) g_pool[j] = 0.f;
    if (idx < 64) g_pcnt[idx] = 0;
}

// ---------------------------------------------------------------- launch
extern "C" void kernel_launch(void* const* d_in, const int* in_sizes, int n_in,
                              void* d_out, int out_size)
{
    bool setup_order = (in_sizes[2] == in_sizes[3]) && (in_sizes[3] == in_sizes[4]);

    const float* x     = (const float*)d_in[0];
    const float* efeat = (const float*)d_in[1];
    const int *etype, *esrc, *edst, *ctype, *bids;
    const float *emb[3], *wh[3], *bhp[3], *wg[3], *bgp[3], *root[3], *bias[3];
    int pbase, eidx, cidx;

    if (setup_order) {
        etype = (const int*)d_in[2];  esrc = (const int*)d_in[3];  edst = (const int*)d_in[4];
        ctype = (const int*)d_in[5];  bids = (const int*)d_in[6];
        pbase = 8; eidx = 2; cidx = 5;
    } else {
        etype = (const int*)d_in[23]; esrc = (const int*)d_in[24]; edst = (const int*)d_in[25];
        ctype = (const int*)d_in[26]; bids = (const int*)d_in[27];
        pbase = 2; eidx = 23; cidx = 26;
    }
    for (int l = 0; l < 3; l++) {
        int b0 = pbase + l * 7;
        emb[l]  = (const float*)d_in[b0];
        wh[l]   = (const float*)d_in[b0 + 1];
        bhp[l]  = (const float*)d_in[b0 + 2];
        wg[l]   = (const float*)d_in[b0 + 3];
        bgp[l]  = (const float*)d_in[b0 + 4];
        root[l] = (const float*)d_in[b0 + 5];
        bias[l] = (const float*)d_in[b0 + 6];
    }
    int E = in_sizes[eidx];
    int N = in_sizes[cidx];
    float* out = (float*)d_out;

    int NBL = (N + 255) / 256;
    int EBL = (E + 255) / 256;

    // CSR build (once per call; graph identical across layers)
    prep_kernel<<<NBL, 256>>>(emb[0], wh[0], bhp[0], wg[0], bgp[0],
                              emb[1], wh[1], bhp[1], wg[1], bgp[1],
                              emb[2], wh[2], bhp[2], wg[2], bgp[2], N);
    hist_kernel   <<<EBL, 256>>>(edst, E);
    scan1_kernel  <<<NBL, 256>>>(N);
    scan2_kernel  <<<1,   256>>>(NBL);
    scan3_kernel  <<<NBL, 256>>>(N, E);
    scatter_kernel<<<EBL, 256>>>(etype, esrc, edst, (const float2*)efeat, E);

    // fused layers (no global atomics in the heavy path)
    const int LB = 296, LT = 256;
    layer_kernel<16, 10, 0, false><<<LB, LT>>>(x, root[0], bias[0], nullptr, nullptr, N);
    layer_kernel<10, 10, 1, false><<<LB, LT>>>(x, root[1], bias[1], nullptr, nullptr, N);
    layer_kernel<10, 16, 2, true ><<<LB, LT>>>(x, root[2], bias[2], ctype, bids, N);

    final_kernel<<<1, 256>>>(out, out_size);
}

// round 8
// speedup vs baseline: 1.1045x; 1.0131x over previous
#include <cuda_runtime.h>

#define NT   25          // edge types
#define NMAX 50176       // node capacity (N=50000)
#define EMAX 250112      // edge capacity (E=250000)
#define GRID 148         // 1 block/SM guaranteed resident (B300=148, GB300=152 SMs)
#define THREADS 512

__device__ float  g_h  [NMAX * 16];
__device__ float  g_h2 [NMAX * 16];
__device__ int    g_rowcnt[NMAX];
__device__ int    g_rowptr[NMAX + 1];
__device__ int    g_wcur  [NMAX];
__device__ int    g_bsum[512];
__device__ int4   g_epack[EMAX];      // CSR-ordered {etype, src, ef0_bits, ef1_bits}
__device__ float  g_pool[64 * 16];
__device__ int    g_pcnt[64];

// ---- software grid barrier (sense-reversing; state returns to initial each pass)
__device__ unsigned g_count = 0;
__device__ volatile unsigned g_gen = 0;

__device__ __forceinline__ void grid_barrier() {
    __syncthreads();
    if (threadIdx.x == 0) {
        __threadfence();                       // release: publish this block's writes
        unsigned my = g_gen;
        if (atomicAdd(&g_count, 1u) == GRID - 1) {
            g_count = 0;
            __threadfence();
            g_gen = my + 1;
        } else {
            while (g_gen == my) __nanosleep(64);
        }
        __threadfence();                       // acquire
    }
    __syncthreads();
}

struct KParams {
    const float*  x;
    const float2* ef;
    const int *etype, *esrc, *edst, *ctype, *bids;
    const float *emb[3], *wh[3], *bh[3], *wg[3], *bg[3], *root[3], *bias[3];
    float* out;
    int N, E, B;
};

// ---- fused layer: build factored tables in smem, gather messages, node update (+pool)
// w[t,i,o](ef) = relu(ef0*C0 + ef1*C1 + C2); C0=emb*wh0+wg0, C1=emb*wh1+wg1, C2=emb*bh+bg
template <int IN, int OUT, bool POOL>
__device__ __forceinline__ void do_layer(
    const float* __restrict__ xin, float* __restrict__ hout,
    const float* __restrict__ emb, const float* __restrict__ wh,
    const float* __restrict__ bh,  const float* __restrict__ wg,
    const float* __restrict__ bg,  const float* __restrict__ root,
    const float* __restrict__ bias,
    const int* __restrict__ ctype, const int* __restrict__ bids,
    float2* sC01, float* sC2, float* s_pool, int* s_cnt, int N, int B)
{
    constexpr int D = IN * OUT;
    for (int j = threadIdx.x; j < NT * D; j += THREADS) {
        int k = j % D;
        float e = __ldg(&emb[j]);
        sC01[j] = make_float2(fmaf(e, __ldg(&wh[k]),     __ldg(&wg[k])),
                              fmaf(e, __ldg(&wh[D + k]), __ldg(&wg[D + k])));
        sC2[j]  = fmaf(e, __ldg(&bh[k]), __ldg(&bg[k]));
    }
    if (POOL) {
        if (threadIdx.x < 64 * 16 && threadIdx.x < 128) s_pool[threadIdx.x] = 0.f;
        if (threadIdx.x < 8) s_cnt[threadIdx.x] = 0;
    }
    __syncthreads();

    int o  = threadIdx.x & 15;
    int oc = (o < OUT) ? o : 0;
    bool lo = (o < IN);
    unsigned gmask = 0xFFFFu << (threadIdx.x & 16);

    float rreg[IN];
#pragma unroll
    for (int i = 0; i < IN; i++) rreg[i] = __ldg(&root[i * OUT + oc]);
    float bv = __ldg(&bias[oc]);

    int group = (blockIdx.x * THREADS + threadIdx.x) >> 4;
    int ng    = (GRID * THREADS) >> 4;

    auto eterm = [&](int4 ep, float xv, float acc) -> float {
        int base = ep.x * D + oc;
        float ef0 = __int_as_float(ep.z), ef1 = __int_as_float(ep.w);
#pragma unroll
        for (int i = 0; i < IN; i++) {
            float2 c = sC01[base + i * OUT];
            float  w = fmaxf(fmaf(ef1, c.y, fmaf(ef0, c.x, sC2[base + i * OUT])), 0.f);
            acc = fmaf(__shfl_sync(gmask, xv, i, 16), w, acc);
        }
        return acc;
    };

    for (int n = group; n < N; n += ng) {
        int r0 = __ldg(&g_rowptr[n]);
        int r1 = __ldg(&g_rowptr[n + 1]);
        float acc0 = 0.f, acc1 = 0.f;

        for (int p = r0; p < r1; p += 4) {
            int m = r1 - p;                        // uniform across the 16-lane group
            int4 ep0, ep1, ep2, ep3;
            ep0 = g_epack[p];
            if (m > 1) ep1 = g_epack[p + 1];
            if (m > 2) ep2 = g_epack[p + 2];
            if (m > 3) ep3 = g_epack[p + 3];
            float xv0 = 0.f, xv1 = 0.f, xv2 = 0.f, xv3 = 0.f;
            if (lo)          xv0 = xin[ep0.y * 16 + o];
            if (m > 1 && lo) xv1 = xin[ep1.y * 16 + o];
            if (m > 2 && lo) xv2 = xin[ep2.y * 16 + o];
            if (m > 3 && lo) xv3 = xin[ep3.y * 16 + o];

            acc0 = eterm(ep0, xv0, acc0);
            if (m > 1) acc1 = eterm(ep1, xv1, acc1);
            if (m > 2) acc0 = eterm(ep2, xv2, acc0);
            if (m > 3) acc1 = eterm(ep3, xv3, acc1);
        }

        int deg = r1 - r0;
        float inv = __frcp_rn((float)(deg > 0 ? deg : 1));
        float a = fmaf(acc0 + acc1, inv, bv);

        float xn = lo ? xin[n * 16 + o] : 0.f;
#pragma unroll
        for (int i = 0; i < IN; i++)
            a = fmaf(__shfl_sync(gmask, xn, i, 16), rreg[i], a);
        a = fmaxf(a, 0.f);

        if (POOL) {
            if (__ldg(&ctype[n]) == 1) {
                int b = __ldg(&bids[n]);
                atomicAdd(&s_pool[b * 16 + o], a);
                if (o == 0) atomicAdd(&s_cnt[b], 1);
            }
        } else {
            if (o < OUT) hout[n * 16 + o] = a;
        }
    }

    if (POOL) {
        __syncthreads();
        if (threadIdx.x < B * 16) {
            float v = s_pool[threadIdx.x];
            if (v != 0.f) atomicAdd(&g_pool[threadIdx.x], v);
        }
        if (threadIdx.x < B) {
            int c = s_cnt[threadIdx.x];
            if (c) atomicAdd(&g_pcnt[threadIdx.x], c);
        }
    }
}

// ---------------------------------------------------------------- the single persistent kernel
__global__ __launch_bounds__(THREADS, 1)
void cellnet_kernel(KParams P)
{
    __shared__ char  smbuf[48000];         // union: scan buffers / C tables
    __shared__ float s_pool[128];
    __shared__ int   s_cnt[8];

    int tid  = threadIdx.x, bid = blockIdx.x;
    int gsz  = GRID * THREADS;
    int gtid = bid * THREADS + tid;
    int N = P.N, E = P.E;

    // ---- phase 0: zero histogram + pool state
    for (int j = gtid; j < N; j += gsz) g_rowcnt[j] = 0;
    if (bid == 0) {
        for (int j = tid; j < 64 * 16; j += THREADS) g_pool[j] = 0.f;
        if (tid < 64) g_pcnt[tid] = 0;
    }
    grid_barrier();

    // ---- phase 1: degree histogram
    for (int e = gtid; e < E; e += gsz) atomicAdd(&g_rowcnt[P.edst[e]], 1);
    grid_barrier();

    // ---- phase 2a: per-chunk sums (chunk = 512 nodes, chunk c -> block c)
    int nch = (N + THREADS - 1) / THREADS;          // <= GRID for N<=75776
    int* sS = (int*)smbuf;
    if (bid < nch) {
        int n  = bid * THREADS + tid;
        int rc = (n < N) ? g_rowcnt[n] : 0;
        sS[tid] = rc; __syncthreads();
        for (int off = THREADS / 2; off > 0; off >>= 1) {
            if (tid < off) sS[tid] += sS[tid + off];
            __syncthreads();
        }
        if (tid == 0) g_bsum[bid] = sS[0];
    }
    grid_barrier();

    // ---- phase 2b: rowptr = scan(bsum)[bid] + intra-chunk exclusive scan
    if (bid < nch) {
        int n  = bid * THREADS + tid;
        int rc = (n < N) ? g_rowcnt[n] : 0;
        int v  = (tid < nch) ? g_bsum[tid] : 0;
        sS[tid] = v; __syncthreads();
        for (int off = 1; off < THREADS; off <<= 1) {
            int u = (tid >= off) ? sS[tid - off] : 0;
            __syncthreads(); sS[tid] += u; __syncthreads();
        }
        int base = (bid == 0) ? 0 : sS[bid - 1];
        int* sT = sS + THREADS;
        sT[tid] = rc; __syncthreads();
        for (int off = 1; off < THREADS; off <<= 1) {
            int u = (tid >= off) ? sT[tid - off] : 0;
            __syncthreads(); sT[tid] += u; __syncthreads();
        }
        int excl = sT[tid] - rc;
        if (n < N) {
            int st = base + excl;
            g_rowptr[n] = st;
            g_wcur[n]   = st;
            if (n == N - 1) g_rowptr[N] = E;
        }
    }
    grid_barrier();

    // ---- phase 3: scatter edges into CSR order
    for (int e = gtid; e < E; e += gsz) {
        int p = atomicAdd(&g_wcur[P.edst[e]], 1);
        float2 f = P.ef[e];
        g_epack[p] = make_int4(P.etype[e], P.esrc[e], __float_as_int(f.x), __float_as_int(f.y));
    }
    grid_barrier();

    // ---- phases 4-6: fused layers
    float2* sC01 = (float2*)smbuf;
    float*  sC2  = (float*)(smbuf + 32000);

    do_layer<16, 10, false>(P.x, g_h,
        P.emb[0], P.wh[0], P.bh[0], P.wg[0], P.bg[0], P.root[0], P.bias[0],
        nullptr, nullptr, sC01, sC2, s_pool, s_cnt, N, P.B);
    grid_barrier();

    do_layer<10, 10, false>(g_h, g_h2,
        P.emb[1], P.wh[1], P.bh[1], P.wg[1], P.bg[1], P.root[1], P.bias[1],
        nullptr, nullptr, sC01, sC2, s_pool, s_cnt, N, P.B);
    grid_barrier();

    do_layer<10, 16, true>(g_h2, nullptr,
        P.emb[2], P.wh[2], P.bh[2], P.wg[2], P.bg[2], P.root[2], P.bias[2],
        P.ctype, P.bids, sC01, sC2, s_pool, s_cnt, N, P.B);
    grid_barrier();

    // ---- phase 7: emit pooled means
    if (bid == 0 && tid < P.B * 16) {
        int b = tid >> 4;
        int c = g_pcnt[b];
        P.out[tid] = g_pool[tid] / (float)(c > 0 ? c : 1);
    }
}

// ---------------------------------------------------------------- launch
extern "C" void kernel_launch(void* const* d_in, const int* in_sizes, int n_in,
                              void* d_out, int out_size)
{
    bool setup_order = (in_sizes[2] == in_sizes[3]) && (in_sizes[3] == in_sizes[4]);

    KParams P;
    P.x  = (const float*)d_in[0];
    P.ef = (const float2*)d_in[1];
    int pbase, eidx, cidx;
    if (setup_order) {
        P.etype = (const int*)d_in[2];  P.esrc = (const int*)d_in[3];  P.edst = (const int*)d_in[4];
        P.ctype = (const int*)d_in[5];  P.bids = (const int*)d_in[6];
        pbase = 8; eidx = 2; cidx = 5;
    } else {
        P.etype = (const int*)d_in[23]; P.esrc = (const int*)d_in[24]; P.edst = (const int*)d_in[25];
        P.ctype = (const int*)d_in[26]; P.bids = (const int*)d_in[27];
        pbase = 2; eidx = 23; cidx = 26;
    }
    for (int l = 0; l < 3; l++) {
        int b0 = pbase + l * 7;
        P.emb[l]  = (const float*)d_in[b0];
        P.wh[l]   = (const float*)d_in[b0 + 1];
        P.bh[l]   = (const float*)d_in[b0 + 2];
        P.wg[l]   = (const float*)d_in[b0 + 3];
        P.bg[l]   = (const float*)d_in[b0 + 4];
        P.root[l] = (const float*)d_in[b0 + 5];
        P.bias[l] = (const float*)d_in[b0 + 6];
    }
    P.E = in_sizes[eidx];
    P.N = in_sizes[cidx];
    P.B = out_size / 16;
    P.out = (float*)d_out;

    cellnet_kernel<<<GRID, THREADS>>>(P);
}